// round 13
// baseline (speedup 1.0000x reference)
#include <cuda_runtime.h>
#include <cuda_fp16.h>
#include <math.h>

#define B_  16
#define L_  128
#define S_  64
#define T_  64
#define QD  1024
#define HD  512
#define OD  512
#define ST_ 4096

typedef unsigned long long u64;
typedef unsigned int u32;

// ---------------- scratch (static device globals) ---------------------------
__device__ __half g_qryh[B_*L_*QD];
__device__ __half g_srch[B_*S_*QD];
__device__ __half g_trgh[B_*T_*QD];
__device__ __half g_qh  [B_*L_*HD];
__device__ __half g_skh [B_*S_*HD];
__device__ __half g_tkh [B_*T_*HD];
__device__ __half g_svh [B_*S_*HD];
__device__ __half g_tvh [B_*T_*HD];
__device__ __half g_svTh[B_*HD*S_];
__device__ __half g_tvTh[B_*HD*T_];
__device__ __half g_wh  [(size_t)B_*L_*ST_];     // half exp(logit) (16.8 MB)
__device__ float  g_rs  [B_*L_];
__device__ __half g_ctxh[B_*L_*HD];
__device__ __half g_parth[64*128*512];           // ctx split-K partials (half)
__device__ float  g_part[2*2048*512];            // out sp0/sp1 partials (fp32)
__device__ __half g_wTh [5*512*1024 + 512*1536]; // half transposed weights

// ---------------- small helpers ---------------------------------------------
__device__ __forceinline__ u32 smem_u32(const void* p){
    u32 a; asm("{ .reg .u64 t; cvta.to.shared.u64 t, %1; cvt.u32.u64 %0, t; }":"=r"(a):"l"(p));
    return a;
}
__device__ __forceinline__ void mma16(float d[4], const u32 a[4], const u32 b[2]){
    asm volatile("mma.sync.aligned.m16n8k16.row.col.f32.f16.f16.f32 "
        "{%0,%1,%2,%3}, {%4,%5,%6,%7}, {%8,%9}, {%0,%1,%2,%3};"
        : "+f"(d[0]),"+f"(d[1]),"+f"(d[2]),"+f"(d[3])
        : "r"(a[0]),"r"(a[1]),"r"(a[2]),"r"(a[3]),"r"(b[0]),"r"(b[1]));
}
#define LDSM4(r0,r1,r2,r3,addr) \
    asm volatile("ldmatrix.sync.aligned.m8n8.x4.shared.b16 {%0,%1,%2,%3}, [%4];" \
        : "=r"(r0),"=r"(r1),"=r"(r2),"=r"(r3) : "r"(addr))
#define CPA16(dst,src) \
    asm volatile("cp.async.cg.shared.global [%0], [%1], 16;"::"r"(dst),"l"(src):"memory")
#define CPA_COMMIT() asm volatile("cp.async.commit_group;":::"memory")
#define CPA_WAITG1() asm volatile("cp.async.wait_group 1;":::"memory")

__device__ __forceinline__ uint4 hmul16(uint4 a, uint4 b){
    __half2* pa=(__half2*)&a; __half2* pb=(__half2*)&b;
    uint4 r; __half2* pr=(__half2*)&r;
    pr[0]=__hmul2(pa[0],pb[0]); pr[1]=__hmul2(pa[1],pb[1]);
    pr[2]=__hmul2(pa[2],pb[2]); pr[3]=__hmul2(pa[3],pb[3]);
    return r;
}
__device__ __forceinline__ uint4 hscale16(uint4 a, __half sc){
    __half2 s2 = __half2half2(sc);
    __half2* pa=(__half2*)&a;
    uint4 r; __half2* pr=(__half2*)&r;
    pr[0]=__hmul2(pa[0],s2); pr[1]=__hmul2(pa[1],s2);
    pr[2]=__hmul2(pa[2],s2); pr[3]=__hmul2(pa[3],s2);
    return r;
}

// 3 slots: A @ slot*16384 (0..48K), B @ 49152 + slot*16384 (48K..96K)
#define SMEM_MMA 98304

#define MMA_PROLOG() \
    int tid=threadIdx.x, lane=tid&31, wid=tid>>5; \
    int wm = wid&3, wn = wid>>2; \
    int gid = lane>>2, tig = lane&3; \
    int l7 = lane&7, lq = lane>>3; \
    u32 smem_u = smem_u32(dsm); \
    int a_sh = lq>>1, b_sh = lq&1; \
    u32 a_row[2], b_row[4]; \
    _Pragma("unroll") \
    for (int mf=0;mf<2;mf++) a_row[mf] = (u32)(wm*32 + mf*16 + (lq&1)*8 + l7)*128u; \
    _Pragma("unroll") \
    for (int p=0;p<4;p++)    b_row[p]  = (u32)(wn*64 + (2*p + (lq>>1))*8 + l7)*128u; \
    int row_[4], seg_[4]; u32 stg_[4]; \
    _Pragma("unroll") \
    for (int j=0;j<4;j++){ int f4 = tid + j*256; row_[j]=f4>>3; seg_[j]=f4&7; \
        stg_[j] = (u32)(row_[j]*128 + ((seg_[j]^(row_[j]&7))<<4)); } \
    float acc[2][8][4]; \
    _Pragma("unroll") \
    for(int mf=0;mf<2;mf++) \
        _Pragma("unroll") \
        for(int nf=0;nf<8;nf++) \
            _Pragma("unroll") \
            for(int r=0;r<4;r++) acc[mf][nf][r]=0.f;

#define MMA_COMPUTE(slot) do { \
    u32 Ab_ = smem_u + (u32)(slot)*16384u; \
    u32 Bb_ = smem_u + 49152u + (u32)(slot)*16384u; \
    _Pragma("unroll") \
    for (int ks=0; ks<4; ks++){ \
        u32 asg = (u32)(((ks*2 + a_sh) ^ l7) << 4); \
        u32 bsg = (u32)(((ks*2 + b_sh) ^ l7) << 4); \
        u32 afr[2][4]; u32 bfr[8][2]; \
        _Pragma("unroll") \
        for (int mf=0;mf<2;mf++) \
            LDSM4(afr[mf][0],afr[mf][1],afr[mf][2],afr[mf][3], Ab_ + a_row[mf] + asg); \
        _Pragma("unroll") \
        for (int p=0;p<4;p++) \
            LDSM4(bfr[2*p][0],bfr[2*p][1],bfr[2*p+1][0],bfr[2*p+1][1], Bb_ + b_row[p] + bsg); \
        _Pragma("unroll") \
        for (int mf=0;mf<2;mf++) \
            _Pragma("unroll") \
            for (int nf=0;nf<8;nf++) mma16(acc[mf][nf], afr[mf], bfr[nf]); \
    } \
} while(0)

#define STS_B(slot, j, v4) \
    *(uint4*)((char*)dsm + 49152 + (u32)(slot)*16384u + stg_[j]) = (v4)

// ===== tri body: wh = exp(Q @ (sk.*tk)^T / sqrt(HD)), rowsum atomics ========
__device__ __forceinline__ void tri_body(const __half* __restrict__ q,
        const __half* __restrict__ sk, const __half* __restrict__ tk,
        __half* __restrict__ w, float* __restrict__ rs, int tile, int b, float* dsm){
    const __half* qb = q + (size_t)b*L_*HD;
    MMA_PROLOG();
    const __half* skp[4]; const __half* tkp[4]; const __half* qp[4];
    #pragma unroll
    for (int j=0;j<4;j++){
        int st = tile*128 + row_[j];
        skp[j] = sk + (size_t)(b*S_ + (st>>6))*HD + seg_[j]*8;
        tkp[j] = tk + (size_t)(b*T_ + (st&63))*HD + seg_[j]*8;
        qp[j]  = qb + (size_t)row_[j]*HD + seg_[j]*8;
    }
    // prologue: tiles 0 and 1
    #pragma unroll
    for (int j=0;j<4;j++) CPA16(smem_u + stg_[j], qp[j]);
    CPA_COMMIT();
    #pragma unroll
    for (int j=0;j<4;j++)
        STS_B(0, j, hmul16(*(const uint4*)tkp[j], *(const uint4*)skp[j]));
    #pragma unroll
    for (int j=0;j<4;j++) CPA16(smem_u + 16384u + stg_[j], qp[j] + 64);
    CPA_COMMIT();
    #pragma unroll
    for (int j=0;j<4;j++)
        STS_B(1, j, hmul16(*(const uint4*)(tkp[j]+64), *(const uint4*)(skp[j]+64)));

    const int NT = HD/64;   // 8
    for (int kt=0; kt<NT; kt++){
        CPA_WAITG1();
        __syncthreads();
        if (kt+2 < NT){
            int kc = (kt+2)*64, s2 = (kt+2)%3;
            u32 nb = smem_u + (u32)s2*16384u;
            #pragma unroll
            for (int j=0;j<4;j++) CPA16(nb + stg_[j], qp[j] + kc);
            CPA_COMMIT();
            #pragma unroll
            for (int j=0;j<4;j++)
                STS_B(s2, j, hmul16(*(const uint4*)(tkp[j]+kc), *(const uint4*)(skp[j]+kc)));
        } else CPA_COMMIT();
        MMA_COMPUTE(kt%3);
    }

    const float scale = 0.044194173824159216f;  // 1/sqrt(512)
    #pragma unroll
    for (int mf=0;mf<2;mf++){
        int row = wm*32 + mf*16 + gid;
        __half* w0 = w + ((size_t)(b*L_+row))*ST_ + tile*128 + wn*64 + tig*2;
        float s0 = 0.f, s1 = 0.f;
        #pragma unroll
        for (int nf=0;nf<8;nf++){
            float e0 = __expf(acc[mf][nf][0]*scale);
            float e1 = __expf(acc[mf][nf][1]*scale);
            float e2 = __expf(acc[mf][nf][2]*scale);
            float e3 = __expf(acc[mf][nf][3]*scale);
            s0 += e0 + e1; s1 += e2 + e3;
            *(__half2*)(w0 + nf*8)          = __floats2half2_rn(e0, e1);
            *(__half2*)(w0 + nf*8 + 8*ST_)  = __floats2half2_rn(e2, e3);
        }
        s0 += __shfl_xor_sync(0xffffffffu, s0, 1);
        s0 += __shfl_xor_sync(0xffffffffu, s0, 2);
        s1 += __shfl_xor_sync(0xffffffffu, s1, 1);
        s1 += __shfl_xor_sync(0xffffffffu, s1, 2);
        if (tig == 0){
            atomicAdd(&rs[b*L_ + row],     s0);
            atomicAdd(&rs[b*L_ + row + 8], s1);
        }
    }
}

// ====== ctx body: parth[b,sp][128l x 128k] = E_chunk @ (svT.*tvT)^T =========
__device__ __forceinline__ void ctx_body(const __half* __restrict__ E,
        const __half* __restrict__ svT, const __half* __restrict__ tvT,
        __half* __restrict__ part, int nt, int sp, int b, float* dsm){
    int n0 = nt*128;
    const __half* Eb  = E   + (size_t)b*L_*ST_ + sp*1024;
    const __half* svb = svT + ((size_t)b*HD + n0)*S_;
    const __half* tvb = tvT + ((size_t)b*HD + n0)*T_;
    MMA_PROLOG();
    const __half* Ep[4]; const __half* svp[4];
    uint4 t4[4];   // hoisted: tv row slice invariant over kt
    #pragma unroll
    for (int j=0;j<4;j++){
        Ep[j]  = Eb + (size_t)row_[j]*ST_ + seg_[j]*8;
        svp[j] = svb + (size_t)row_[j]*S_ + sp*16;
        t4[j]  = *(const uint4*)(tvb + (size_t)row_[j]*T_ + seg_[j]*8);
    }
    // prologue: tiles 0 and 1
    #pragma unroll
    for (int j=0;j<4;j++) CPA16(smem_u + stg_[j], Ep[j]);
    CPA_COMMIT();
    #pragma unroll
    for (int j=0;j<4;j++) STS_B(0, j, hscale16(t4[j], svp[j][0]));
    #pragma unroll
    for (int j=0;j<4;j++) CPA16(smem_u + 16384u + stg_[j], Ep[j] + 64);
    CPA_COMMIT();
    #pragma unroll
    for (int j=0;j<4;j++) STS_B(1, j, hscale16(t4[j], svp[j][1]));

    const int NT = 1024/64;  // 16
    for (int kt=0; kt<NT; kt++){
        CPA_WAITG1();
        __syncthreads();
        if (kt+2 < NT){
            int kc = (kt+2)*64, s2 = (kt+2)%3;
            u32 nb = smem_u + (u32)s2*16384u;
            #pragma unroll
            for (int j=0;j<4;j++) CPA16(nb + stg_[j], Ep[j] + kc);
            CPA_COMMIT();
            #pragma unroll
            for (int j=0;j<4;j++) STS_B(s2, j, hscale16(t4[j], svp[j][kt+2]));
        } else CPA_COMMIT();
        MMA_COMPUTE(kt%3);
    }

    #pragma unroll
    for (int mf=0;mf<2;mf++){
        int row = wm*32 + mf*16 + gid;
        __half* p0 = part + ((size_t)(b*4+sp)*128 + row)*512 + n0 + wn*64 + tig*2;
        #pragma unroll
        for (int nf=0;nf<8;nf++){
            *(__half2*)(p0 + nf*8)         = __floats2half2_rn(acc[mf][nf][0], acc[mf][nf][1]);
            *(__half2*)(p0 + nf*8 + 8*512) = __floats2half2_rn(acc[mf][nf][2], acc[mf][nf][3]);
        }
    }
}

// ===== pure-copy GEMM loop (A and B via cp.async, 3-stage) ==================
#define COPY_LOOP(NT, ApExpr, BpExpr) \
    { \
        _Pragma("unroll") \
        for (int j=0;j<4;j++){ CPA16(smem_u + stg_[j], (ApExpr)); CPA16(smem_u + 49152u + stg_[j], (BpExpr)); } \
        CPA_COMMIT(); \
    } \
    { \
        const int kc = 64; \
        _Pragma("unroll") \
        for (int j=0;j<4;j++){ CPA16(smem_u + 16384u + stg_[j], (ApExpr) + kc); CPA16(smem_u + 49152u + 16384u + stg_[j], (BpExpr) + kc); } \
        CPA_COMMIT(); \
    } \
    for (int kt=0; kt<(NT); kt++){ \
        CPA_WAITG1(); \
        __syncthreads(); \
        if (kt+2 < (NT)){ \
            int kc = (kt+2)*64, s2 = (kt+2)%3; \
            u32 nbA = smem_u + (u32)s2*16384u; \
            u32 nbB = nbA + 49152u; \
            _Pragma("unroll") \
            for (int j=0;j<4;j++){ CPA16(nbA + stg_[j], (ApExpr) + kc); CPA16(nbB + stg_[j], (BpExpr) + kc); } \
            CPA_COMMIT(); \
        } else CPA_COMMIT(); \
        MMA_COMPUTE(kt%3); \
    }

// ===== out partial body (sp 0/1): fp32 partials of query-half GEMM ==========
__device__ __forceinline__ void out_part_body(const __half* __restrict__ query,
        const __half* __restrict__ WoT, float* __restrict__ part,
        int bnI, int bmI, int sp, float* dsm){
    int bn = bnI*128, bm = bmI*128;
    const __half* Ab = query + (size_t)bm*QD + sp*512;
    const __half* Bw = WoT + (size_t)bn*1536 + sp*512;
    MMA_PROLOG();
    const __half* Ap[4]; const __half* Bp[4];
    #pragma unroll
    for (int j=0;j<4;j++){
        Ap[j] = Ab + (size_t)row_[j]*QD + seg_[j]*8;
        Bp[j] = Bw + (size_t)row_[j]*1536 + seg_[j]*8;
    }
    COPY_LOOP(8, Ap[j], Bp[j]);

    #pragma unroll
    for (int mf=0;mf<2;mf++){
        int row = wm*32 + mf*16 + gid;
        float* p0 = part + ((size_t)sp*2048 + bm + row)*512 + bn + wn*64 + tig*2;
        #pragma unroll
        for (int nf=0;nf<8;nf++){
            *(float2*)(p0 + nf*8)         = make_float2(acc[mf][nf][0], acc[mf][nf][1]);
            *(float2*)(p0 + nf*8 + 8*512) = make_float2(acc[mf][nf][2], acc[mf][nf][3]);
        }
    }
}

// ===== out final (sp=2, ctx-half) + fused reduce of sp0/sp1 + bias + relu ===
__global__ __launch_bounds__(256,2) void out_final_kernel(const __half* __restrict__ ctx,
        const __half* __restrict__ WoT, const float* __restrict__ part,
        const float* __restrict__ bo, float* __restrict__ out){
    extern __shared__ __align__(16) float dsm[];
    int bn = blockIdx.x*128, bm = blockIdx.y*128;
    const __half* Ab = ctx + (size_t)bm*HD;
    const __half* Bw = WoT + (size_t)bn*1536 + 2*512;
    MMA_PROLOG();
    const __half* Ap[4]; const __half* Bp[4];
    #pragma unroll
    for (int j=0;j<4;j++){
        Ap[j] = Ab + (size_t)row_[j]*HD + seg_[j]*8;
        Bp[j] = Bw + (size_t)row_[j]*1536 + seg_[j]*8;
    }
    COPY_LOOP(8, Ap[j], Bp[j]);

    const float* bp = bo + bn + wn*64 + tig*2;
    #pragma unroll
    for (int mf=0;mf<2;mf++){
        int row = wm*32 + mf*16 + gid;
        int m0 = bm + row;
        const float* q0 = part + (size_t)m0*512 + bn + wn*64 + tig*2;
        const float* q1 = part + (size_t)(2048 + m0)*512 + bn + wn*64 + tig*2;
        float* o0 = out + (size_t)m0*OD + bn + wn*64 + tig*2;
        #pragma unroll
        for (int nf=0;nf<8;nf++){
            float b0 = bp[nf*8], b1 = bp[nf*8+1];
            {   float2 pA = *(const float2*)(q0 + nf*8);
                float2 pB = *(const float2*)(q1 + nf*8);
                *(float2*)(o0 + nf*8) = make_float2(
                    fmaxf(acc[mf][nf][0] + pA.x + pB.x + b0, 0.f),
                    fmaxf(acc[mf][nf][1] + pA.y + pB.y + b1, 0.f));
            }
            {   float2 pA = *(const float2*)(q0 + nf*8 + 8*512);
                float2 pB = *(const float2*)(q1 + nf*8 + 8*512);
                *(float2*)(o0 + nf*8 + 8*OD) = make_float2(
                    fmaxf(acc[mf][nf][2] + pA.x + pB.x + b0, 0.f),
                    fmaxf(acc[mf][nf][3] + pA.y + pB.y + b1, 0.f));
            }
        }
    }
}

// -------- transpose_vals body (uses dynamic smem) ---------------------------
__device__ __forceinline__ void tvals_body(const __half* __restrict__ sv,
        const __half* __restrict__ tv, __half* __restrict__ svT, __half* __restrict__ tvT,
        int k0t, int b, int z, float* dsm){
    __half (*tilebuf)[65] = ( __half(*)[65] )dsm;
    int k0 = k0t*64;
    const __half* src = z ? tv : sv;
    __half* dst = z ? tvT : svT;
    int tid = threadIdx.x;
    #pragma unroll
    for (int j = 0; j < 16; j++){
        int e = tid + j*256, s = e>>6, k = e&63;
        tilebuf[k][s] = src[(size_t)(b*64 + s)*HD + k0 + k];
    }
    __syncthreads();
    #pragma unroll
    for (int j = 0; j < 16; j++){
        int e = tid + j*256, k = e>>6, s = e&63;
        dst[(size_t)(b*HD + k0 + k)*64 + s] = tilebuf[k][s];
    }
}

// ============ merged launch 3: tri (512 blocks) + transpose_vals (256) ======
__global__ __launch_bounds__(256,2) void l3_kernel(const __half* __restrict__ q,
        const __half* __restrict__ sk, const __half* __restrict__ tk,
        __half* __restrict__ w, float* __restrict__ rs, const __half* __restrict__ sv,
        const __half* __restrict__ tv, __half* __restrict__ svT, __half* __restrict__ tvT){
    extern __shared__ __align__(16) float dsm[];
    int bx = blockIdx.x;
    if (bx < 512){
        tri_body(q, sk, tk, w, rs, bx & 31, bx >> 5, dsm);
    } else {
        int local = bx - 512;
        tvals_body(sv, tv, svT, tvT, local & 7, (local >> 3) & 15, local >> 7, dsm);
    }
}

// ============ merged launch 4: ctx (256 blocks) + out sp0,1 (128) ===========
__global__ __launch_bounds__(256,2) void l5_kernel(const __half* __restrict__ E,
        const __half* __restrict__ svT, const __half* __restrict__ tvT,
        __half* __restrict__ cpart, const __half* __restrict__ query,
        const __half* __restrict__ WoT, float* __restrict__ opart){
    extern __shared__ __align__(16) float dsm[];
    int bx = blockIdx.x;
    if (bx < 256){
        int nt = bx & 3, sp = (bx >> 2) & 3, b = bx >> 4;
        ctx_body(E, svT, tvT, cpart, nt, sp, b, dsm);
    } else {
        int local = bx - 256;
        out_part_body(query, WoT, opart, local & 3, (local >> 2) & 15, local >> 6, dsm);
    }
}

// ============ projections: C = A[Mx1024] @ W + bias (half out) ==============
struct ProjArgs {
    const __half* A[5];
    const __half* WT[5];
    const float*  bias[5];
    __half*       C[5];
};

__global__ __launch_bounds__(256,2) void proj_mma(ProjArgs args){
    extern __shared__ __align__(16) float dsm[];
    int y = blockIdx.y;
    int task, mt;
    if (y < 16){ task=0; mt=y; } else { task = 1 + ((y-16)>>3); mt = (y-16)&7; }
    int bm = mt*128, bn = blockIdx.x*128;
    const __half* Ab   = args.A[task]  + (size_t)bm*QD;
    const __half* Bw   = args.WT[task] + (size_t)bn*QD;
    const float*  bias = args.bias[task];
    __half*       C    = args.C[task]  + (size_t)bm*OD + bn;
    MMA_PROLOG();
    const __half* Ap[4]; const __half* Bp[4];
    #pragma unroll
    for (int j=0;j<4;j++){
        Ap[j] = Ab + (size_t)row_[j]*QD + seg_[j]*8;
        Bp[j] = Bw + (size_t)row_[j]*QD + seg_[j]*8;
    }
    COPY_LOOP(16, Ap[j], Bp[j]);

    const float* bp = bias + bn + wn*64 + tig*2;
    #pragma unroll
    for (int mf=0;mf<2;mf++){
        int row = wm*32 + mf*16 + gid;
        __half* c0 = C + (size_t)row*OD + wn*64 + tig*2;
        #pragma unroll
        for (int nf=0;nf<8;nf++){
            float b0 = bp[nf*8], b1 = bp[nf*8+1];
            *(__half2*)(c0 + nf*8)        = __floats2half2_rn(acc[mf][nf][0]+b0, acc[mf][nf][1]+b1);
            *(__half2*)(c0 + nf*8 + 8*OD) = __floats2half2_rn(acc[mf][nf][2]+b0, acc[mf][nf][3]+b1);
        }
    }
}

// -------- prep: cvt inputs (4096) + transpose weights (1152) + zero rs ------
struct PrepArgs {
    const float* q; const float* s; const float* t;
    __half* qh; __half* sh; __half* th;
    const float* wsrc[6]; __half* wdst[6]; int K[6];
    float* rs;
};
__global__ void prep_kernel(PrepArgs a){
    __shared__ float tb[64][65];
    int bx = blockIdx.x, tid = threadIdx.x;
    if (bx < 4096){
        if (bx == 0){
            #pragma unroll
            for (int i=0;i<8;i++) a.rs[tid + i*256] = 0.f;
        }
        int gid = bx*256 + tid;
        const float4* src; uint2* dst; int off;
        if (gid < 524288){ src=(const float4*)a.q; dst=(uint2*)a.qh; off=gid; }
        else if (gid < 786432){ src=(const float4*)a.s; dst=(uint2*)a.sh; off=gid-524288; }
        else { src=(const float4*)a.t; dst=(uint2*)a.th; off=gid-786432; }
        float4 v = src[off];
        uint2 r; __half2* pr=(__half2*)&r;
        pr[0]=__floats2half2_rn(v.x,v.y); pr[1]=__floats2half2_rn(v.z,v.w);
        dst[off]=r;
    } else {
        int local = bx - 4096;
        int mid = local / 192;
        int rem = local % 192;
        int k0 = (rem >> 3) * 64;
        int n0 = (rem & 7) * 64;
        int K = a.K[mid];
        if (k0 >= K) return;
        const float* src = a.wsrc[mid];
        __half* dst = a.wdst[mid];
        #pragma unroll
        for (int j=0;j<16;j++){
            int e = tid + j*256, kk = e>>6, nn = e&63;
            tb[nn][kk] = src[(size_t)(k0+kk)*512 + n0+nn];
        }
        __syncthreads();
        #pragma unroll
        for (int j=0;j<16;j++){
            int e = tid + j*256, nn = e>>6, kk = e&63;
            dst[(size_t)(n0+nn)*K + k0+kk] = __float2half(tb[nn][kk]);
        }
    }
}

// reduce the 4 half split-K partials, apply 1/rowsum, emit half ctx
__global__ void ctx_reduce(const __half* __restrict__ part, const float* __restrict__ rs,
                           __half* __restrict__ ctx){
    int gid = blockIdx.x*256 + threadIdx.x;       // 4-elem id over 16*128*128
    int n4 = gid & 127; int rest = gid >> 7; int l = rest & 127; int b = rest >> 7;
    const uint2* p = (const uint2*)part;
    float a0=0,a1=0,a2=0,a3=0;
    #pragma unroll
    for (int sp=0; sp<4; sp++){
        uint2 u = p[ ((size_t)(b*4+sp)*128 + l)*128 + n4 ];
        __half2* pu = (__half2*)&u;
        float2 x = __half22float2(pu[0]), y = __half22float2(pu[1]);
        a0+=x.x; a1+=x.y; a2+=y.x; a3+=y.y;
    }
    float inv = 1.f / rs[b*128 + l];
    uint2 r; __half2* pr=(__half2*)&r;
    pr[0]=__floats2half2_rn(a0*inv, a1*inv); pr[1]=__floats2half2_rn(a2*inv, a3*inv);
    ((uint2*)ctx)[gid] = r;
}

// ----------------------------------------------------------------------------
extern "C" void kernel_launch(void* const* d_in, const int* in_sizes, int n_in,
                              void* d_out, int out_size) {
    const float* query = (const float*)d_in[0];
    const float* src   = (const float*)d_in[1];
    const float* trg   = (const float*)d_in[2];
    const float* Wq    = (const float*)d_in[3];
    const float* bq    = (const float*)d_in[4];
    const float* Ws    = (const float*)d_in[5];
    const float* bs    = (const float*)d_in[6];
    const float* Wt    = (const float*)d_in[7];
    const float* bt    = (const float*)d_in[8];
    const float* Wsv   = (const float*)d_in[9];
    const float* bsv   = (const float*)d_in[10];
    const float* Wtv   = (const float*)d_in[11];
    const float* btv   = (const float*)d_in[12];
    const float* Wo    = (const float*)d_in[13];
    const float* bo    = (const float*)d_in[14];
    float* out = (float*)d_out;

    __half *qryh,*srch,*trgh,*qh,*skh,*tkh,*svh,*tvh,*svTh,*tvTh,*wh,*ctxh,*wTh,*cparth;
    float *grs,*gpart;
    cudaGetSymbolAddress((void**)&qryh, g_qryh);
    cudaGetSymbolAddress((void**)&srch, g_srch);
    cudaGetSymbolAddress((void**)&trgh, g_trgh);
    cudaGetSymbolAddress((void**)&qh,   g_qh);
    cudaGetSymbolAddress((void**)&skh,  g_skh);
    cudaGetSymbolAddress((void**)&tkh,  g_tkh);
    cudaGetSymbolAddress((void**)&svh,  g_svh);
    cudaGetSymbolAddress((void**)&tvh,  g_tvh);
    cudaGetSymbolAddress((void**)&svTh, g_svTh);
    cudaGetSymbolAddress((void**)&tvTh, g_tvTh);
    cudaGetSymbolAddress((void**)&wh,   g_wh);
    cudaGetSymbolAddress((void**)&ctxh, g_ctxh);
    cudaGetSymbolAddress((void**)&wTh,  g_wTh);
    cudaGetSymbolAddress((void**)&cparth, g_parth);
    cudaGetSymbolAddress((void**)&grs,  g_rs);
    cudaGetSymbolAddress((void**)&gpart,g_part);

    static int smem_set = 0;
    if (!smem_set){
        cudaFuncSetAttribute(l3_kernel,       cudaFuncAttributeMaxDynamicSharedMemorySize, SMEM_MMA);
        cudaFuncSetAttribute(l5_kernel,       cudaFuncAttributeMaxDynamicSharedMemorySize, SMEM_MMA);
        cudaFuncSetAttribute(out_final_kernel,cudaFuncAttributeMaxDynamicSharedMemorySize, SMEM_MMA);
        cudaFuncSetAttribute(proj_mma,        cudaFuncAttributeMaxDynamicSharedMemorySize, SMEM_MMA);
        smem_set = 1;
    }

    __half* WqT  = wTh;
    __half* WsT  = wTh + 1*512*1024;
    __half* WtT  = wTh + 2*512*1024;
    __half* WsvT = wTh + 3*512*1024;
    __half* WtvT = wTh + 4*512*1024;
    __half* WoT  = wTh + 5*512*1024;

    PrepArgs pr;
    pr.q=query; pr.s=src; pr.t=trg; pr.qh=qryh; pr.sh=srch; pr.th=trgh;
    pr.wsrc[0]=Wq;  pr.wdst[0]=WqT;  pr.K[0]=1024;
    pr.wsrc[1]=Ws;  pr.wdst[1]=WsT;  pr.K[1]=1024;
    pr.wsrc[2]=Wt;  pr.wdst[2]=WtT;  pr.K[2]=1024;
    pr.wsrc[3]=Wsv; pr.wdst[3]=WsvT; pr.K[3]=1024;
    pr.wsrc[4]=Wtv; pr.wdst[4]=WtvT; pr.K[4]=1024;
    pr.wsrc[5]=Wo;  pr.wdst[5]=WoT;  pr.K[5]=1536;
    pr.rs = grs;

    ProjArgs pa;
    pa.A[0]=qryh;  pa.A[1]=srch; pa.A[2]=trgh; pa.A[3]=srch;  pa.A[4]=trgh;
    pa.WT[0]=WqT;  pa.WT[1]=WsT; pa.WT[2]=WtT; pa.WT[3]=WsvT; pa.WT[4]=WtvT;
    pa.bias[0]=bq; pa.bias[1]=bs; pa.bias[2]=bt; pa.bias[3]=bsv; pa.bias[4]=btv;
    pa.C[0]=qh;    pa.C[1]=skh;  pa.C[2]=tkh;  pa.C[3]=svh;   pa.C[4]=tvh;

    prep_kernel     <<<4096+1152,  256>>>(pr);
    proj_mma        <<<dim3(4,48), 256, SMEM_MMA>>>(pa);
    l3_kernel       <<<768,        256, SMEM_MMA>>>(qh, skh, tkh, wh, grs, svh, tvh, svTh, tvTh);
    l5_kernel       <<<384,        256, SMEM_MMA>>>(wh, svTh, tvTh, cparth, qryh, WoT, gpart);
    ctx_reduce      <<<1024,       256>>>(cparth, grs, ctxh);
    out_final_kernel<<<dim3(4,16), 256, SMEM_MMA>>>(ctxh, WoT, gpart, bo, out);
}

// round 14
// speedup vs baseline: 1.0303x; 1.0303x over previous
#include <cuda_runtime.h>
#include <cuda_fp16.h>
#include <math.h>

#define B_  16
#define L_  128
#define S_  64
#define T_  64
#define QD  1024
#define HD  512
#define OD  512
#define ST_ 4096

typedef unsigned long long u64;
typedef unsigned int u32;

// ---------------- scratch (static device globals) ---------------------------
__device__ __half g_qryh[B_*L_*QD];
__device__ __half g_srch[B_*S_*QD];
__device__ __half g_trgh[B_*T_*QD];
__device__ __half g_qh  [B_*L_*HD];
__device__ __half g_skh [B_*S_*HD];
__device__ __half g_tkh [B_*T_*HD];
__device__ __half g_svh [B_*S_*HD];
__device__ __half g_tvh [B_*T_*HD];
__device__ __half g_svTh[B_*HD*S_];
__device__ __half g_tvTh[B_*HD*T_];
__device__ __half g_wh  [(size_t)B_*L_*ST_];     // half exp(logit) (16.8 MB)
__device__ float  g_rs  [B_*L_];
__device__ __half g_ctxh[B_*L_*HD];
__device__ __half g_parth[32*128*512];           // ctx split-K=2 partials (half)
__device__ float  g_part[2*2048*512];            // out sp0/sp1 partials (fp32)
__device__ __half g_wTh [5*512*1024 + 512*1536]; // half transposed weights

// ---------------- small helpers ---------------------------------------------
__device__ __forceinline__ u32 smem_u32(const void* p){
    u32 a; asm("{ .reg .u64 t; cvta.to.shared.u64 t, %1; cvt.u32.u64 %0, t; }":"=r"(a):"l"(p));
    return a;
}
__device__ __forceinline__ void mma16(float d[4], const u32 a[4], const u32 b[2]){
    asm volatile("mma.sync.aligned.m16n8k16.row.col.f32.f16.f16.f32 "
        "{%0,%1,%2,%3}, {%4,%5,%6,%7}, {%8,%9}, {%0,%1,%2,%3};"
        : "+f"(d[0]),"+f"(d[1]),"+f"(d[2]),"+f"(d[3])
        : "r"(a[0]),"r"(a[1]),"r"(a[2]),"r"(a[3]),"r"(b[0]),"r"(b[1]));
}
#define LDSM4(r0,r1,r2,r3,addr) \
    asm volatile("ldmatrix.sync.aligned.m8n8.x4.shared.b16 {%0,%1,%2,%3}, [%4];" \
        : "=r"(r0),"=r"(r1),"=r"(r2),"=r"(r3) : "r"(addr))
#define CPA16(dst,src) \
    asm volatile("cp.async.cg.shared.global [%0], [%1], 16;"::"r"(dst),"l"(src):"memory")
#define CPA_COMMIT() asm volatile("cp.async.commit_group;":::"memory")
#define CPA_WAIT0()  asm volatile("cp.async.wait_group 0;":::"memory")

__device__ __forceinline__ uint4 hmul16(uint4 a, uint4 b){
    __half2* pa=(__half2*)&a; __half2* pb=(__half2*)&b;
    uint4 r; __half2* pr=(__half2*)&r;
    pr[0]=__hmul2(pa[0],pb[0]); pr[1]=__hmul2(pa[1],pb[1]);
    pr[2]=__hmul2(pa[2],pb[2]); pr[3]=__hmul2(pa[3],pb[3]);
    return r;
}
__device__ __forceinline__ uint4 hscale16(uint4 a, __half sc){
    __half2 s2 = __half2half2(sc);
    __half2* pa=(__half2*)&a;
    uint4 r; __half2* pr=(__half2*)&r;
    pr[0]=__hmul2(pa[0],s2); pr[1]=__hmul2(pa[1],s2);
    pr[2]=__hmul2(pa[2],s2); pr[3]=__hmul2(pa[3],s2);
    return r;
}

#define SMEM_MMA 65536

#define MMA_PROLOG() \
    int tid=threadIdx.x, lane=tid&31, wid=tid>>5; \
    int wm = wid&3, wn = wid>>2; \
    int gid = lane>>2, tig = lane&3; \
    int l7 = lane&7, lq = lane>>3; \
    u32 smem_u = smem_u32(dsm); \
    int a_sh = lq>>1, b_sh = lq&1; \
    u32 a_row[2], b_row[4]; \
    _Pragma("unroll") \
    for (int mf=0;mf<2;mf++) a_row[mf] = (u32)(wm*32 + mf*16 + (lq&1)*8 + l7)*128u; \
    _Pragma("unroll") \
    for (int p=0;p<4;p++)    b_row[p]  = (u32)(wn*64 + (2*p + (lq>>1))*8 + l7)*128u; \
    int row_[4], seg_[4]; u32 stg_[4]; \
    _Pragma("unroll") \
    for (int j=0;j<4;j++){ int f4 = tid + j*256; row_[j]=f4>>3; seg_[j]=f4&7; \
        stg_[j] = (u32)(row_[j]*128 + ((seg_[j]^(row_[j]&7))<<4)); } \
    float acc[2][8][4]; \
    _Pragma("unroll") \
    for(int mf=0;mf<2;mf++) \
        _Pragma("unroll") \
        for(int nf=0;nf<8;nf++) \
            _Pragma("unroll") \
            for(int r=0;r<4;r++) acc[mf][nf][r]=0.f;

#define MMA_COMPUTE(slot) do { \
    u32 Ab_ = smem_u + (u32)(slot)*16384u; \
    u32 Bb_ = smem_u + 32768u + (u32)(slot)*16384u; \
    _Pragma("unroll") \
    for (int ks=0; ks<4; ks++){ \
        u32 asg = (u32)(((ks*2 + a_sh) ^ l7) << 4); \
        u32 bsg = (u32)(((ks*2 + b_sh) ^ l7) << 4); \
        u32 afr[2][4]; u32 bfr[8][2]; \
        _Pragma("unroll") \
        for (int mf=0;mf<2;mf++) \
            LDSM4(afr[mf][0],afr[mf][1],afr[mf][2],afr[mf][3], Ab_ + a_row[mf] + asg); \
        _Pragma("unroll") \
        for (int p=0;p<4;p++) \
            LDSM4(bfr[2*p][0],bfr[2*p][1],bfr[2*p+1][0],bfr[2*p+1][1], Bb_ + b_row[p] + bsg); \
        _Pragma("unroll") \
        for (int mf=0;mf<2;mf++) \
            _Pragma("unroll") \
            for (int nf=0;nf<8;nf++) mma16(acc[mf][nf], afr[mf], bfr[nf]); \
    } \
} while(0)

#define STS_B(slot, j, v4) \
    *(uint4*)((char*)dsm + 32768 + (u32)(slot)*16384u + stg_[j]) = (v4)

// ===== tri body: wh = exp(Q @ (sk.*tk)^T / sqrt(HD)), rowsum atomics ========
__device__ __forceinline__ void tri_body(const __half* __restrict__ q,
        const __half* __restrict__ sk, const __half* __restrict__ tk,
        __half* __restrict__ w, float* __restrict__ rs, int tile, int b, float* dsm){
    const __half* qb = q + (size_t)b*L_*HD;
    MMA_PROLOG();
    const __half* skp[4]; const __half* tkp[4]; const __half* qp[4];
    #pragma unroll
    for (int j=0;j<4;j++){
        int st = tile*128 + row_[j];
        skp[j] = sk + (size_t)(b*S_ + (st>>6))*HD + seg_[j]*8;
        tkp[j] = tk + (size_t)(b*T_ + (st&63))*HD + seg_[j]*8;
        qp[j]  = qb + (size_t)row_[j]*HD + seg_[j]*8;
    }
    #pragma unroll
    for (int j=0;j<4;j++) CPA16(smem_u + stg_[j], qp[j]);
    CPA_COMMIT();
    uint4 pb[4];
    #pragma unroll
    for (int j=0;j<4;j++)
        pb[j] = hmul16(*(const uint4*)tkp[j], *(const uint4*)skp[j]);
    #pragma unroll
    for (int j=0;j<4;j++) STS_B(0, j, pb[j]);
    CPA_WAIT0();
    __syncthreads();

    const int NT = HD/64;   // 8
    for (int kt=0; kt<NT; kt++){
        int slot = kt&1;
        if (kt+1 < NT){
            int kc = (kt+1)*64;
            u32 nb = smem_u + (u32)(slot^1)*16384u;
            #pragma unroll
            for (int j=0;j<4;j++) CPA16(nb + stg_[j], qp[j] + kc);
            CPA_COMMIT();
            #pragma unroll
            for (int j=0;j<4;j++)
                pb[j] = hmul16(*(const uint4*)(tkp[j]+kc), *(const uint4*)(skp[j]+kc));
        }
        MMA_COMPUTE(slot);
        if (kt+1 < NT){
            #pragma unroll
            for (int j=0;j<4;j++) STS_B(slot^1, j, pb[j]);
            CPA_WAIT0();
        }
        __syncthreads();
    }

    const float scale = 0.044194173824159216f;  // 1/sqrt(512)
    #pragma unroll
    for (int mf=0;mf<2;mf++){
        int row = wm*32 + mf*16 + gid;
        __half* w0 = w + ((size_t)(b*L_+row))*ST_ + tile*128 + wn*64 + tig*2;
        float s0 = 0.f, s1 = 0.f;
        #pragma unroll
        for (int nf=0;nf<8;nf++){
            float e0 = __expf(acc[mf][nf][0]*scale);
            float e1 = __expf(acc[mf][nf][1]*scale);
            float e2 = __expf(acc[mf][nf][2]*scale);
            float e3 = __expf(acc[mf][nf][3]*scale);
            s0 += e0 + e1; s1 += e2 + e3;
            *(__half2*)(w0 + nf*8)          = __floats2half2_rn(e0, e1);
            *(__half2*)(w0 + nf*8 + 8*ST_)  = __floats2half2_rn(e2, e3);
        }
        s0 += __shfl_xor_sync(0xffffffffu, s0, 1);
        s0 += __shfl_xor_sync(0xffffffffu, s0, 2);
        s1 += __shfl_xor_sync(0xffffffffu, s1, 1);
        s1 += __shfl_xor_sync(0xffffffffu, s1, 2);
        if (tig == 0){
            atomicAdd(&rs[b*L_ + row],     s0);
            atomicAdd(&rs[b*L_ + row + 8], s1);
        }
    }
}

// == ctx body: parth[b,sp][128l x 128k] = E_chunk @ (svT.*tvT)^T, sp in {0,1}
__device__ __forceinline__ void ctx_body(const __half* __restrict__ E,
        const __half* __restrict__ svT, const __half* __restrict__ tvT,
        __half* __restrict__ part, int nt, int sp, int b, float* dsm){
    int n0 = nt*128;
    const __half* Eb  = E   + (size_t)b*L_*ST_ + sp*2048;
    const __half* svb = svT + ((size_t)b*HD + n0)*S_;
    const __half* tvb = tvT + ((size_t)b*HD + n0)*T_;
    MMA_PROLOG();
    const __half* Ep[4]; const __half* svp[4];
    uint4 t4[4];   // tv row slice invariant over kt
    #pragma unroll
    for (int j=0;j<4;j++){
        Ep[j]  = Eb + (size_t)row_[j]*ST_ + seg_[j]*8;
        svp[j] = svb + (size_t)row_[j]*S_ + sp*32;
        t4[j]  = *(const uint4*)(tvb + (size_t)row_[j]*T_ + seg_[j]*8);
    }
    #pragma unroll
    for (int j=0;j<4;j++) CPA16(smem_u + stg_[j], Ep[j]);
    CPA_COMMIT();
    #pragma unroll
    for (int j=0;j<4;j++) STS_B(0, j, hscale16(t4[j], svp[j][0]));
    CPA_WAIT0();
    __syncthreads();

    const int NT = 2048/64;  // 32
    for (int kt=0; kt<NT; kt++){
        int slot = kt&1;
        if (kt+1 < NT){
            int kc = (kt+1)*64;
            u32 nb = smem_u + (u32)(slot^1)*16384u;
            #pragma unroll
            for (int j=0;j<4;j++) CPA16(nb + stg_[j], Ep[j] + kc);
            CPA_COMMIT();
        }
        MMA_COMPUTE(slot);
        if (kt+1 < NT){
            #pragma unroll
            for (int j=0;j<4;j++) STS_B(slot^1, j, hscale16(t4[j], svp[j][kt+1]));
            CPA_WAIT0();
        }
        __syncthreads();
    }

    #pragma unroll
    for (int mf=0;mf<2;mf++){
        int row = wm*32 + mf*16 + gid;
        __half* p0 = part + ((size_t)(b*2+sp)*128 + row)*512 + n0 + wn*64 + tig*2;
        #pragma unroll
        for (int nf=0;nf<8;nf++){
            *(__half2*)(p0 + nf*8)         = __floats2half2_rn(acc[mf][nf][0], acc[mf][nf][1]);
            *(__half2*)(p0 + nf*8 + 8*512) = __floats2half2_rn(acc[mf][nf][2], acc[mf][nf][3]);
        }
    }
}

// ===== pure-copy GEMM loop (A and B via cp.async, 2-stage) ==================
#define COPY_LOOP(NT, ApExpr, BpExpr) \
    { \
        _Pragma("unroll") \
        for (int j=0;j<4;j++){ CPA16(smem_u + stg_[j], (ApExpr)); CPA16(smem_u + 32768u + stg_[j], (BpExpr)); } \
        CPA_COMMIT(); CPA_WAIT0(); \
        __syncthreads(); \
    } \
    for (int kt=0; kt<(NT); kt++){ \
        int slot = kt&1; \
        if (kt+1 < (NT)){ \
            int kc = (kt+1)*64; \
            u32 nbA = smem_u + (u32)(slot^1)*16384u; \
            u32 nbB = nbA + 32768u; \
            _Pragma("unroll") \
            for (int j=0;j<4;j++){ CPA16(nbA + stg_[j], (ApExpr) + kc); CPA16(nbB + stg_[j], (BpExpr) + kc); } \
            CPA_COMMIT(); \
        } \
        MMA_COMPUTE(slot); \
        if (kt+1 < (NT)) CPA_WAIT0(); \
        __syncthreads(); \
    }

// ===== out partial body (sp 0/1): fp32 partials of query-half GEMM ==========
__device__ __forceinline__ void out_part_body(const __half* __restrict__ query,
        const __half* __restrict__ WoT, float* __restrict__ part,
        int bnI, int bmI, int sp, float* dsm){
    int bn = bnI*128, bm = bmI*128;
    const __half* Ab = query + (size_t)bm*QD + sp*512;
    const __half* Bw = WoT + (size_t)bn*1536 + sp*512;
    MMA_PROLOG();
    const __half* Ap[4]; const __half* Bp[4];
    #pragma unroll
    for (int j=0;j<4;j++){
        Ap[j] = Ab + (size_t)row_[j]*QD + seg_[j]*8;
        Bp[j] = Bw + (size_t)row_[j]*1536 + seg_[j]*8;
    }
    COPY_LOOP(8, Ap[j], Bp[j]);

    #pragma unroll
    for (int mf=0;mf<2;mf++){
        int row = wm*32 + mf*16 + gid;
        float* p0 = part + ((size_t)sp*2048 + bm + row)*512 + bn + wn*64 + tig*2;
        #pragma unroll
        for (int nf=0;nf<8;nf++){
            *(float2*)(p0 + nf*8)         = make_float2(acc[mf][nf][0], acc[mf][nf][1]);
            *(float2*)(p0 + nf*8 + 8*512) = make_float2(acc[mf][nf][2], acc[mf][nf][3]);
        }
    }
}

// ===== out final (sp=2, ctx-half) + fused reduce of sp0/sp1 + bias + relu ===
__global__ __launch_bounds__(256,2) void out_final_kernel(const __half* __restrict__ ctx,
        const __half* __restrict__ WoT, const float* __restrict__ part,
        const float* __restrict__ bo, float* __restrict__ out){
    extern __shared__ __align__(16) float dsm[];
    int bn = blockIdx.x*128, bm = blockIdx.y*128;
    const __half* Ab = ctx + (size_t)bm*HD;
    const __half* Bw = WoT + (size_t)bn*1536 + 2*512;
    MMA_PROLOG();
    const __half* Ap[4]; const __half* Bp[4];
    #pragma unroll
    for (int j=0;j<4;j++){
        Ap[j] = Ab + (size_t)row_[j]*HD + seg_[j]*8;
        Bp[j] = Bw + (size_t)row_[j]*1536 + seg_[j]*8;
    }
    COPY_LOOP(8, Ap[j], Bp[j]);

    const float* bp = bo + bn + wn*64 + tig*2;
    #pragma unroll
    for (int mf=0;mf<2;mf++){
        int row = wm*32 + mf*16 + gid;
        int m0 = bm + row;
        const float* q0 = part + (size_t)m0*512 + bn + wn*64 + tig*2;
        const float* q1 = part + (size_t)(2048 + m0)*512 + bn + wn*64 + tig*2;
        float* o0 = out + (size_t)m0*OD + bn + wn*64 + tig*2;
        #pragma unroll
        for (int nf=0;nf<8;nf++){
            float b0 = bp[nf*8], b1 = bp[nf*8+1];
            {   float2 pA = *(const float2*)(q0 + nf*8);
                float2 pB = *(const float2*)(q1 + nf*8);
                *(float2*)(o0 + nf*8) = make_float2(
                    fmaxf(acc[mf][nf][0] + pA.x + pB.x + b0, 0.f),
                    fmaxf(acc[mf][nf][1] + pA.y + pB.y + b1, 0.f));
            }
            {   float2 pA = *(const float2*)(q0 + nf*8 + 8*512);
                float2 pB = *(const float2*)(q1 + nf*8 + 8*512);
                *(float2*)(o0 + nf*8 + 8*OD) = make_float2(
                    fmaxf(acc[mf][nf][2] + pA.x + pB.x + b0, 0.f),
                    fmaxf(acc[mf][nf][3] + pA.y + pB.y + b1, 0.f));
            }
        }
    }
}

// -------- transpose_vals body (uses dynamic smem) ---------------------------
__device__ __forceinline__ void tvals_body(const __half* __restrict__ sv,
        const __half* __restrict__ tv, __half* __restrict__ svT, __half* __restrict__ tvT,
        int k0t, int b, int z, float* dsm){
    __half (*tilebuf)[65] = ( __half(*)[65] )dsm;
    int k0 = k0t*64;
    const __half* src = z ? tv : sv;
    __half* dst = z ? tvT : svT;
    int tid = threadIdx.x;
    #pragma unroll
    for (int j = 0; j < 16; j++){
        int e = tid + j*256, s = e>>6, k = e&63;
        tilebuf[k][s] = src[(size_t)(b*64 + s)*HD + k0 + k];
    }
    __syncthreads();
    #pragma unroll
    for (int j = 0; j < 16; j++){
        int e = tid + j*256, k = e>>6, s = e&63;
        dst[(size_t)(b*HD + k0 + k)*64 + s] = tilebuf[k][s];
    }
}

// ============ merged launch 3: tri (512 blocks) + transpose_vals (256) ======
__global__ __launch_bounds__(256,2) void l3_kernel(const __half* __restrict__ q,
        const __half* __restrict__ sk, const __half* __restrict__ tk,
        __half* __restrict__ w, float* __restrict__ rs, const __half* __restrict__ sv,
        const __half* __restrict__ tv, __half* __restrict__ svT, __half* __restrict__ tvT){
    extern __shared__ __align__(16) float dsm[];
    int bx = blockIdx.x;
    if (bx < 512){
        tri_body(q, sk, tk, w, rs, bx & 31, bx >> 5, dsm);
    } else {
        int local = bx - 512;
        tvals_body(sv, tv, svT, tvT, local & 7, (local >> 3) & 15, local >> 7, dsm);
    }
}

// ============ merged launch 4: ctx (128 blocks) + out sp0,1 (128) ===========
__global__ __launch_bounds__(256,2) void l5_kernel(const __half* __restrict__ E,
        const __half* __restrict__ svT, const __half* __restrict__ tvT,
        __half* __restrict__ cpart, const __half* __restrict__ query,
        const __half* __restrict__ WoT, float* __restrict__ opart){
    extern __shared__ __align__(16) float dsm[];
    int bx = blockIdx.x;
    if (bx < 128){
        int nt = bx & 3, sp = (bx >> 2) & 1, b = bx >> 3;
        ctx_body(E, svT, tvT, cpart, nt, sp, b, dsm);
    } else {
        int local = bx - 128;
        out_part_body(query, WoT, opart, local & 3, (local >> 2) & 15, local >> 6, dsm);
    }
}

// ============ projections: C = A[Mx1024] @ W + bias (half out) ==============
struct ProjArgs {
    const __half* A[5];
    const __half* WT[5];
    const float*  bias[5];
    __half*       C[5];
};

__global__ __launch_bounds__(256,2) void proj_mma(ProjArgs args){
    extern __shared__ __align__(16) float dsm[];
    int y = blockIdx.y;
    int task, mt;
    if (y < 16){ task=0; mt=y; } else { task = 1 + ((y-16)>>3); mt = (y-16)&7; }
    int bm = mt*128, bn = blockIdx.x*128;
    const __half* Ab   = args.A[task]  + (size_t)bm*QD;
    const __half* Bw   = args.WT[task] + (size_t)bn*QD;
    const float*  bias = args.bias[task];
    __half*       C    = args.C[task]  + (size_t)bm*OD + bn;
    MMA_PROLOG();
    const __half* Ap[4]; const __half* Bp[4];
    #pragma unroll
    for (int j=0;j<4;j++){
        Ap[j] = Ab + (size_t)row_[j]*QD + seg_[j]*8;
        Bp[j] = Bw + (size_t)row_[j]*QD + seg_[j]*8;
    }
    COPY_LOOP(16, Ap[j], Bp[j]);

    const float* bp = bias + bn + wn*64 + tig*2;
    #pragma unroll
    for (int mf=0;mf<2;mf++){
        int row = wm*32 + mf*16 + gid;
        __half* c0 = C + (size_t)row*OD + wn*64 + tig*2;
        #pragma unroll
        for (int nf=0;nf<8;nf++){
            float b0 = bp[nf*8], b1 = bp[nf*8+1];
            *(__half2*)(c0 + nf*8)        = __floats2half2_rn(acc[mf][nf][0]+b0, acc[mf][nf][1]+b1);
            *(__half2*)(c0 + nf*8 + 8*OD) = __floats2half2_rn(acc[mf][nf][2]+b0, acc[mf][nf][3]+b1);
        }
    }
}

// -------- prep: cvt inputs (4096) + transpose weights (1152) + zero rs ------
struct PrepArgs {
    const float* q; const float* s; const float* t;
    __half* qh; __half* sh; __half* th;
    const float* wsrc[6]; __half* wdst[6]; int K[6];
    float* rs;
};
__global__ void prep_kernel(PrepArgs a){
    __shared__ float tb[64][65];
    int bx = blockIdx.x, tid = threadIdx.x;
    if (bx < 4096){
        if (bx == 0){
            #pragma unroll
            for (int i=0;i<8;i++) a.rs[tid + i*256] = 0.f;
        }
        int gid = bx*256 + tid;
        const float4* src; uint2* dst; int off;
        if (gid < 524288){ src=(const float4*)a.q; dst=(uint2*)a.qh; off=gid; }
        else if (gid < 786432){ src=(const float4*)a.s; dst=(uint2*)a.sh; off=gid-524288; }
        else { src=(const float4*)a.t; dst=(uint2*)a.th; off=gid-786432; }
        float4 v = src[off];
        uint2 r; __half2* pr=(__half2*)&r;
        pr[0]=__floats2half2_rn(v.x,v.y); pr[1]=__floats2half2_rn(v.z,v.w);
        dst[off]=r;
    } else {
        int local = bx - 4096;
        int mid = local / 192;
        int rem = local % 192;
        int k0 = (rem >> 3) * 64;
        int n0 = (rem & 7) * 64;
        int K = a.K[mid];
        if (k0 >= K) return;
        const float* src = a.wsrc[mid];
        __half* dst = a.wdst[mid];
        #pragma unroll
        for (int j=0;j<16;j++){
            int e = tid + j*256, kk = e>>6, nn = e&63;
            tb[nn][kk] = src[(size_t)(k0+kk)*512 + n0+nn];
        }
        __syncthreads();
        #pragma unroll
        for (int j=0;j<16;j++){
            int e = tid + j*256, nn = e>>6, kk = e&63;
            dst[(size_t)(n0+nn)*K + k0+kk] = __float2half(tb[nn][kk]);
        }
    }
}

// reduce the 2 half split-K partials, apply 1/rowsum, emit half ctx
__global__ void ctx_reduce(const __half* __restrict__ part, const float* __restrict__ rs,
                           __half* __restrict__ ctx){
    int gid = blockIdx.x*256 + threadIdx.x;       // 4-elem id over 16*128*128
    int n4 = gid & 127; int rest = gid >> 7; int l = rest & 127; int b = rest >> 7;
    const uint2* p = (const uint2*)part;
    float a0=0,a1=0,a2=0,a3=0;
    #pragma unroll
    for (int sp=0; sp<2; sp++){
        uint2 u = p[ ((size_t)(b*2+sp)*128 + l)*128 + n4 ];
        __half2* pu = (__half2*)&u;
        float2 x = __half22float2(pu[0]), y = __half22float2(pu[1]);
        a0+=x.x; a1+=x.y; a2+=y.x; a3+=y.y;
    }
    float inv = 1.f / rs[b*128 + l];
    uint2 r; __half2* pr=(__half2*)&r;
    pr[0]=__floats2half2_rn(a0*inv, a1*inv); pr[1]=__floats2half2_rn(a2*inv, a3*inv);
    ((uint2*)ctx)[gid] = r;
}

// ----------------------------------------------------------------------------
extern "C" void kernel_launch(void* const* d_in, const int* in_sizes, int n_in,
                              void* d_out, int out_size) {
    const float* query = (const float*)d_in[0];
    const float* src   = (const float*)d_in[1];
    const float* trg   = (const float*)d_in[2];
    const float* Wq    = (const float*)d_in[3];
    const float* bq    = (const float*)d_in[4];
    const float* Ws    = (const float*)d_in[5];
    const float* bs    = (const float*)d_in[6];
    const float* Wt    = (const float*)d_in[7];
    const float* bt    = (const float*)d_in[8];
    const float* Wsv   = (const float*)d_in[9];
    const float* bsv   = (const float*)d_in[10];
    const float* Wtv   = (const float*)d_in[11];
    const float* btv   = (const float*)d_in[12];
    const float* Wo    = (const float*)d_in[13];
    const float* bo    = (const float*)d_in[14];
    float* out = (float*)d_out;

    __half *qryh,*srch,*trgh,*qh,*skh,*tkh,*svh,*tvh,*svTh,*tvTh,*wh,*ctxh,*wTh,*cparth;
    float *grs,*gpart;
    cudaGetSymbolAddress((void**)&qryh, g_qryh);
    cudaGetSymbolAddress((void**)&srch, g_srch);
    cudaGetSymbolAddress((void**)&trgh, g_trgh);
    cudaGetSymbolAddress((void**)&qh,   g_qh);
    cudaGetSymbolAddress((void**)&skh,  g_skh);
    cudaGetSymbolAddress((void**)&tkh,  g_tkh);
    cudaGetSymbolAddress((void**)&svh,  g_svh);
    cudaGetSymbolAddress((void**)&tvh,  g_tvh);
    cudaGetSymbolAddress((void**)&svTh, g_svTh);
    cudaGetSymbolAddress((void**)&tvTh, g_tvTh);
    cudaGetSymbolAddress((void**)&wh,   g_wh);
    cudaGetSymbolAddress((void**)&ctxh, g_ctxh);
    cudaGetSymbolAddress((void**)&wTh,  g_wTh);
    cudaGetSymbolAddress((void**)&cparth, g_parth);
    cudaGetSymbolAddress((void**)&grs,  g_rs);
    cudaGetSymbolAddress((void**)&gpart,g_part);

    static int smem_set = 0;
    if (!smem_set){
        cudaFuncSetAttribute(l3_kernel,       cudaFuncAttributeMaxDynamicSharedMemorySize, SMEM_MMA);
        cudaFuncSetAttribute(l5_kernel,       cudaFuncAttributeMaxDynamicSharedMemorySize, SMEM_MMA);
        cudaFuncSetAttribute(out_final_kernel,cudaFuncAttributeMaxDynamicSharedMemorySize, SMEM_MMA);
        cudaFuncSetAttribute(proj_mma,        cudaFuncAttributeMaxDynamicSharedMemorySize, SMEM_MMA);
        smem_set = 1;
    }

    __half* WqT  = wTh;
    __half* WsT  = wTh + 1*512*1024;
    __half* WtT  = wTh + 2*512*1024;
    __half* WsvT = wTh + 3*512*1024;
    __half* WtvT = wTh + 4*512*1024;
    __half* WoT  = wTh + 5*512*1024;

    PrepArgs pr;
    pr.q=query; pr.s=src; pr.t=trg; pr.qh=qryh; pr.sh=srch; pr.th=trgh;
    pr.wsrc[0]=Wq;  pr.wdst[0]=WqT;  pr.K[0]=1024;
    pr.wsrc[1]=Ws;  pr.wdst[1]=WsT;  pr.K[1]=1024;
    pr.wsrc[2]=Wt;  pr.wdst[2]=WtT;  pr.K[2]=1024;
    pr.wsrc[3]=Wsv; pr.wdst[3]=WsvT; pr.K[3]=1024;
    pr.wsrc[4]=Wtv; pr.wdst[4]=WtvT; pr.K[4]=1024;
    pr.wsrc[5]=Wo;  pr.wdst[5]=WoT;  pr.K[5]=1536;
    pr.rs = grs;

    ProjArgs pa;
    pa.A[0]=qryh;  pa.A[1]=srch; pa.A[2]=trgh; pa.A[3]=srch;  pa.A[4]=trgh;
    pa.WT[0]=WqT;  pa.WT[1]=WsT; pa.WT[2]=WtT; pa.WT[3]=WsvT; pa.WT[4]=WtvT;
    pa.bias[0]=bq; pa.bias[1]=bs; pa.bias[2]=bt; pa.bias[3]=bsv; pa.bias[4]=btv;
    pa.C[0]=qh;    pa.C[1]=skh;  pa.C[2]=tkh;  pa.C[3]=svh;   pa.C[4]=tvh;

    prep_kernel     <<<4096+1152,  256>>>(pr);
    proj_mma        <<<dim3(4,48), 256, SMEM_MMA>>>(pa);
    l3_kernel       <<<768,        256, SMEM_MMA>>>(qh, skh, tkh, wh, grs, svh, tvh, svTh, tvTh);
    l5_kernel       <<<256,        256, SMEM_MMA>>>(wh, svTh, tvTh, cparth, qryh, WoT, gpart);
    ctx_reduce      <<<1024,       256>>>(cparth, grs, ctxh);
    out_final_kernel<<<dim3(4,16), 256, SMEM_MMA>>>(ctxh, WoT, gpart, bo, out);
}

// round 15
// speedup vs baseline: 1.0368x; 1.0063x over previous
#include <cuda_runtime.h>
#include <cuda_fp16.h>
#include <math.h>

#define B_  16
#define L_  128
#define S_  64
#define T_  64
#define QD  1024
#define HD  512
#define OD  512
#define ST_ 4096

typedef unsigned long long u64;
typedef unsigned int u32;

// ---------------- scratch (static device globals) ---------------------------
__device__ __half g_qryh[B_*L_*QD];
__device__ __half g_srch[B_*S_*QD];
__device__ __half g_trgh[B_*T_*QD];
__device__ __half g_qh  [B_*L_*HD];
__device__ __half g_skh [B_*S_*HD];
__device__ __half g_tkh [B_*T_*HD];
__device__ __half g_svh [B_*S_*HD];
__device__ __half g_tvh [B_*T_*HD];
__device__ __half g_svTh[B_*HD*S_];
__device__ __half g_tvTh[B_*HD*T_];
__device__ __half g_wh  [(size_t)B_*L_*ST_];     // half exp(logit) (16.8 MB)
__device__ float  g_rs  [B_*L_];
__device__ __half g_ctxh[B_*L_*HD];
__device__ __half g_parth[64*128*512];           // ctx split-K=4 partials (half)
__device__ float  g_part[2*2048*512];            // out sp0/sp1 partials (fp32)
__device__ __half g_wTh [5*512*1024 + 512*1536]; // half transposed weights

// ---------------- small helpers ---------------------------------------------
__device__ __forceinline__ u32 smem_u32(const void* p){
    u32 a; asm("{ .reg .u64 t; cvta.to.shared.u64 t, %1; cvt.u32.u64 %0, t; }":"=r"(a):"l"(p));
    return a;
}
__device__ __forceinline__ void mma16(float d[4], const u32 a[4], const u32 b[2]){
    asm volatile("mma.sync.aligned.m16n8k16.row.col.f32.f16.f16.f32 "
        "{%0,%1,%2,%3}, {%4,%5,%6,%7}, {%8,%9}, {%0,%1,%2,%3};"
        : "+f"(d[0]),"+f"(d[1]),"+f"(d[2]),"+f"(d[3])
        : "r"(a[0]),"r"(a[1]),"r"(a[2]),"r"(a[3]),"r"(b[0]),"r"(b[1]));
}
#define LDSM4(r0,r1,r2,r3,addr) \
    asm volatile("ldmatrix.sync.aligned.m8n8.x4.shared.b16 {%0,%1,%2,%3}, [%4];" \
        : "=r"(r0),"=r"(r1),"=r"(r2),"=r"(r3) : "r"(addr))
#define CPA16(dst,src) \
    asm volatile("cp.async.cg.shared.global [%0], [%1], 16;"::"r"(dst),"l"(src):"memory")
#define CPA_COMMIT() asm volatile("cp.async.commit_group;":::"memory")
#define CPA_WAIT0()  asm volatile("cp.async.wait_group 0;":::"memory")

__device__ __forceinline__ uint4 hmul16(uint4 a, uint4 b){
    __half2* pa=(__half2*)&a; __half2* pb=(__half2*)&b;
    uint4 r; __half2* pr=(__half2*)&r;
    pr[0]=__hmul2(pa[0],pb[0]); pr[1]=__hmul2(pa[1],pb[1]);
    pr[2]=__hmul2(pa[2],pb[2]); pr[3]=__hmul2(pa[3],pb[3]);
    return r;
}
__device__ __forceinline__ uint4 hscale16(uint4 a, __half sc){
    __half2 s2 = __half2half2(sc);
    __half2* pa=(__half2*)&a;
    uint4 r; __half2* pr=(__half2*)&r;
    pr[0]=__hmul2(pa[0],s2); pr[1]=__hmul2(pa[1],s2);
    pr[2]=__hmul2(pa[2],s2); pr[3]=__hmul2(pa[3],s2);
    return r;
}

#define SMEM_MMA 65536

#define MMA_PROLOG() \
    int tid=threadIdx.x, lane=tid&31, wid=tid>>5; \
    int wm = wid&3, wn = wid>>2; \
    int gid = lane>>2, tig = lane&3; \
    int l7 = lane&7, lq = lane>>3; \
    u32 smem_u = smem_u32(dsm); \
    int a_sh = lq>>1, b_sh = lq&1; \
    u32 a_row[2], b_row[4]; \
    _Pragma("unroll") \
    for (int mf=0;mf<2;mf++) a_row[mf] = (u32)(wm*32 + mf*16 + (lq&1)*8 + l7)*128u; \
    _Pragma("unroll") \
    for (int p=0;p<4;p++)    b_row[p]  = (u32)(wn*64 + (2*p + (lq>>1))*8 + l7)*128u; \
    int row_[4], seg_[4]; u32 stg_[4]; \
    _Pragma("unroll") \
    for (int j=0;j<4;j++){ int f4 = tid + j*256; row_[j]=f4>>3; seg_[j]=f4&7; \
        stg_[j] = (u32)(row_[j]*128 + ((seg_[j]^(row_[j]&7))<<4)); } \
    float acc[2][8][4]; \
    _Pragma("unroll") \
    for(int mf=0;mf<2;mf++) \
        _Pragma("unroll") \
        for(int nf=0;nf<8;nf++) \
            _Pragma("unroll") \
            for(int r=0;r<4;r++) acc[mf][nf][r]=0.f;

#define MMA_COMPUTE(slot) do { \
    u32 Ab_ = smem_u + (u32)(slot)*16384u; \
    u32 Bb_ = smem_u + 32768u + (u32)(slot)*16384u; \
    _Pragma("unroll") \
    for (int ks=0; ks<4; ks++){ \
        u32 asg = (u32)(((ks*2 + a_sh) ^ l7) << 4); \
        u32 bsg = (u32)(((ks*2 + b_sh) ^ l7) << 4); \
        u32 afr[2][4]; u32 bfr[8][2]; \
        _Pragma("unroll") \
        for (int mf=0;mf<2;mf++) \
            LDSM4(afr[mf][0],afr[mf][1],afr[mf][2],afr[mf][3], Ab_ + a_row[mf] + asg); \
        _Pragma("unroll") \
        for (int p=0;p<4;p++) \
            LDSM4(bfr[2*p][0],bfr[2*p][1],bfr[2*p+1][0],bfr[2*p+1][1], Bb_ + b_row[p] + bsg); \
        _Pragma("unroll") \
        for (int mf=0;mf<2;mf++) \
            _Pragma("unroll") \
            for (int nf=0;nf<8;nf++) mma16(acc[mf][nf], afr[mf], bfr[nf]); \
    } \
} while(0)

#define STS_B(slot, j, v4) \
    *(uint4*)((char*)dsm + 32768 + (u32)(slot)*16384u + stg_[j]) = (v4)

// ===== tri body: wh = exp(Q @ (sk.*tk)^T / sqrt(HD)), rowsum atomics ========
__device__ __forceinline__ void tri_body(const __half* __restrict__ q,
        const __half* __restrict__ sk, const __half* __restrict__ tk,
        __half* __restrict__ w, float* __restrict__ rs, int tile, int b, float* dsm){
    const __half* qb = q + (size_t)b*L_*HD;
    MMA_PROLOG();
    const __half* skp[4]; const __half* tkp[4]; const __half* qp[4];
    #pragma unroll
    for (int j=0;j<4;j++){
        int st = tile*128 + row_[j];
        skp[j] = sk + (size_t)(b*S_ + (st>>6))*HD + seg_[j]*8;
        tkp[j] = tk + (size_t)(b*T_ + (st&63))*HD + seg_[j]*8;
        qp[j]  = qb + (size_t)row_[j]*HD + seg_[j]*8;
    }
    #pragma unroll
    for (int j=0;j<4;j++) CPA16(smem_u + stg_[j], qp[j]);
    CPA_COMMIT();
    uint4 pb[4];
    #pragma unroll
    for (int j=0;j<4;j++)
        pb[j] = hmul16(*(const uint4*)tkp[j], *(const uint4*)skp[j]);
    #pragma unroll
    for (int j=0;j<4;j++) STS_B(0, j, pb[j]);
    CPA_WAIT0();
    __syncthreads();

    const int NT = HD/64;   // 8
    for (int kt=0; kt<NT; kt++){
        int slot = kt&1;
        if (kt+1 < NT){
            int kc = (kt+1)*64;
            u32 nb = smem_u + (u32)(slot^1)*16384u;
            #pragma unroll
            for (int j=0;j<4;j++) CPA16(nb + stg_[j], qp[j] + kc);
            CPA_COMMIT();
            #pragma unroll
            for (int j=0;j<4;j++)
                pb[j] = hmul16(*(const uint4*)(tkp[j]+kc), *(const uint4*)(skp[j]+kc));
        }
        MMA_COMPUTE(slot);
        if (kt+1 < NT){
            #pragma unroll
            for (int j=0;j<4;j++) STS_B(slot^1, j, pb[j]);
            CPA_WAIT0();
        }
        __syncthreads();
    }

    const float scale = 0.044194173824159216f;  // 1/sqrt(512)
    #pragma unroll
    for (int mf=0;mf<2;mf++){
        int row = wm*32 + mf*16 + gid;
        __half* w0 = w + ((size_t)(b*L_+row))*ST_ + tile*128 + wn*64 + tig*2;
        float s0 = 0.f, s1 = 0.f;
        #pragma unroll
        for (int nf=0;nf<8;nf++){
            float e0 = __expf(acc[mf][nf][0]*scale);
            float e1 = __expf(acc[mf][nf][1]*scale);
            float e2 = __expf(acc[mf][nf][2]*scale);
            float e3 = __expf(acc[mf][nf][3]*scale);
            s0 += e0 + e1; s1 += e2 + e3;
            *(__half2*)(w0 + nf*8)          = __floats2half2_rn(e0, e1);
            *(__half2*)(w0 + nf*8 + 8*ST_)  = __floats2half2_rn(e2, e3);
        }
        s0 += __shfl_xor_sync(0xffffffffu, s0, 1);
        s0 += __shfl_xor_sync(0xffffffffu, s0, 2);
        s1 += __shfl_xor_sync(0xffffffffu, s1, 1);
        s1 += __shfl_xor_sync(0xffffffffu, s1, 2);
        if (tig == 0){
            atomicAdd(&rs[b*L_ + row],     s0);
            atomicAdd(&rs[b*L_ + row + 8], s1);
        }
    }
}

// == ctx body: parth[b,sp][128l x 128k] = E_chunk @ (svT.*tvT)^T, sp in 0..3 =
__device__ __forceinline__ void ctx_body(const __half* __restrict__ E,
        const __half* __restrict__ svT, const __half* __restrict__ tvT,
        __half* __restrict__ part, int nt, int sp, int b, float* dsm){
    int n0 = nt*128;
    const __half* Eb  = E   + (size_t)b*L_*ST_ + sp*1024;
    const __half* svb = svT + ((size_t)b*HD + n0)*S_;
    const __half* tvb = tvT + ((size_t)b*HD + n0)*T_;
    MMA_PROLOG();
    const __half* Ep[4]; const __half* svp[4];
    uint4 t4[4];   // tv row slice invariant over kt
    #pragma unroll
    for (int j=0;j<4;j++){
        Ep[j]  = Eb + (size_t)row_[j]*ST_ + seg_[j]*8;
        svp[j] = svb + (size_t)row_[j]*S_ + sp*16;
        t4[j]  = *(const uint4*)(tvb + (size_t)row_[j]*T_ + seg_[j]*8);
    }
    #pragma unroll
    for (int j=0;j<4;j++) CPA16(smem_u + stg_[j], Ep[j]);
    CPA_COMMIT();
    #pragma unroll
    for (int j=0;j<4;j++) STS_B(0, j, hscale16(t4[j], svp[j][0]));
    CPA_WAIT0();
    __syncthreads();

    const int NT = 1024/64;  // 16
    for (int kt=0; kt<NT; kt++){
        int slot = kt&1;
        if (kt+1 < NT){
            int kc = (kt+1)*64;
            u32 nb = smem_u + (u32)(slot^1)*16384u;
            #pragma unroll
            for (int j=0;j<4;j++) CPA16(nb + stg_[j], Ep[j] + kc);
            CPA_COMMIT();
        }
        MMA_COMPUTE(slot);
        if (kt+1 < NT){
            #pragma unroll
            for (int j=0;j<4;j++) STS_B(slot^1, j, hscale16(t4[j], svp[j][kt+1]));
            CPA_WAIT0();
        }
        __syncthreads();
    }

    #pragma unroll
    for (int mf=0;mf<2;mf++){
        int row = wm*32 + mf*16 + gid;
        __half* p0 = part + ((size_t)(b*4+sp)*128 + row)*512 + n0 + wn*64 + tig*2;
        #pragma unroll
        for (int nf=0;nf<8;nf++){
            *(__half2*)(p0 + nf*8)         = __floats2half2_rn(acc[mf][nf][0], acc[mf][nf][1]);
            *(__half2*)(p0 + nf*8 + 8*512) = __floats2half2_rn(acc[mf][nf][2], acc[mf][nf][3]);
        }
    }
}

// ===== pure-copy GEMM loop (A and B via cp.async, 2-stage) ==================
#define COPY_LOOP(NT, ApExpr, BpExpr) \
    { \
        _Pragma("unroll") \
        for (int j=0;j<4;j++){ CPA16(smem_u + stg_[j], (ApExpr)); CPA16(smem_u + 32768u + stg_[j], (BpExpr)); } \
        CPA_COMMIT(); CPA_WAIT0(); \
        __syncthreads(); \
    } \
    for (int kt=0; kt<(NT); kt++){ \
        int slot = kt&1; \
        if (kt+1 < (NT)){ \
            int kc = (kt+1)*64; \
            u32 nbA = smem_u + (u32)(slot^1)*16384u; \
            u32 nbB = nbA + 32768u; \
            _Pragma("unroll") \
            for (int j=0;j<4;j++){ CPA16(nbA + stg_[j], (ApExpr) + kc); CPA16(nbB + stg_[j], (BpExpr) + kc); } \
            CPA_COMMIT(); \
        } \
        MMA_COMPUTE(slot); \
        if (kt+1 < (NT)) CPA_WAIT0(); \
        __syncthreads(); \
    }

// ===== out partial body (sp 0/1): fp32 partials of query-half GEMM ==========
__device__ __forceinline__ void out_part_body(const __half* __restrict__ query,
        const __half* __restrict__ WoT, float* __restrict__ part,
        int bnI, int bmI, int sp, float* dsm){
    int bn = bnI*128, bm = bmI*128;
    const __half* Ab = query + (size_t)bm*QD + sp*512;
    const __half* Bw = WoT + (size_t)bn*1536 + sp*512;
    MMA_PROLOG();
    const __half* Ap[4]; const __half* Bp[4];
    #pragma unroll
    for (int j=0;j<4;j++){
        Ap[j] = Ab + (size_t)row_[j]*QD + seg_[j]*8;
        Bp[j] = Bw + (size_t)row_[j]*1536 + seg_[j]*8;
    }
    COPY_LOOP(8, Ap[j], Bp[j]);

    #pragma unroll
    for (int mf=0;mf<2;mf++){
        int row = wm*32 + mf*16 + gid;
        float* p0 = part + ((size_t)sp*2048 + bm + row)*512 + bn + wn*64 + tig*2;
        #pragma unroll
        for (int nf=0;nf<8;nf++){
            *(float2*)(p0 + nf*8)         = make_float2(acc[mf][nf][0], acc[mf][nf][1]);
            *(float2*)(p0 + nf*8 + 8*512) = make_float2(acc[mf][nf][2], acc[mf][nf][3]);
        }
    }
}

// ===== out final (sp=2, ctx-half) + fused reduce of sp0/sp1 + bias + relu ===
__global__ __launch_bounds__(256,2) void out_final_kernel(const __half* __restrict__ ctx,
        const __half* __restrict__ WoT, const float* __restrict__ part,
        const float* __restrict__ bo, float* __restrict__ out){
    extern __shared__ __align__(16) float dsm[];
    int bn = blockIdx.x*128, bm = blockIdx.y*128;
    const __half* Ab = ctx + (size_t)bm*HD;
    const __half* Bw = WoT + (size_t)bn*1536 + 2*512;
    MMA_PROLOG();
    const __half* Ap[4]; const __half* Bp[4];
    #pragma unroll
    for (int j=0;j<4;j++){
        Ap[j] = Ab + (size_t)row_[j]*HD + seg_[j]*8;
        Bp[j] = Bw + (size_t)row_[j]*1536 + seg_[j]*8;
    }
    COPY_LOOP(8, Ap[j], Bp[j]);

    const float* bp = bo + bn + wn*64 + tig*2;
    #pragma unroll
    for (int mf=0;mf<2;mf++){
        int row = wm*32 + mf*16 + gid;
        int m0 = bm + row;
        const float* q0 = part + (size_t)m0*512 + bn + wn*64 + tig*2;
        const float* q1 = part + (size_t)(2048 + m0)*512 + bn + wn*64 + tig*2;
        float* o0 = out + (size_t)m0*OD + bn + wn*64 + tig*2;
        #pragma unroll
        for (int nf=0;nf<8;nf++){
            float b0 = bp[nf*8], b1 = bp[nf*8+1];
            {   float2 pA = *(const float2*)(q0 + nf*8);
                float2 pB = *(const float2*)(q1 + nf*8);
                *(float2*)(o0 + nf*8) = make_float2(
                    fmaxf(acc[mf][nf][0] + pA.x + pB.x + b0, 0.f),
                    fmaxf(acc[mf][nf][1] + pA.y + pB.y + b1, 0.f));
            }
            {   float2 pA = *(const float2*)(q0 + nf*8 + 8*512);
                float2 pB = *(const float2*)(q1 + nf*8 + 8*512);
                *(float2*)(o0 + nf*8 + 8*OD) = make_float2(
                    fmaxf(acc[mf][nf][2] + pA.x + pB.x + b0, 0.f),
                    fmaxf(acc[mf][nf][3] + pA.y + pB.y + b1, 0.f));
            }
        }
    }
}

// -------- transpose_vals body (uses dynamic smem) ---------------------------
__device__ __forceinline__ void tvals_body(const __half* __restrict__ sv,
        const __half* __restrict__ tv, __half* __restrict__ svT, __half* __restrict__ tvT,
        int k0t, int b, int z, float* dsm){
    __half (*tilebuf)[65] = ( __half(*)[65] )dsm;
    int k0 = k0t*64;
    const __half* src = z ? tv : sv;
    __half* dst = z ? tvT : svT;
    int tid = threadIdx.x;
    #pragma unroll
    for (int j = 0; j < 16; j++){
        int e = tid + j*256, s = e>>6, k = e&63;
        tilebuf[k][s] = src[(size_t)(b*64 + s)*HD + k0 + k];
    }
    __syncthreads();
    #pragma unroll
    for (int j = 0; j < 16; j++){
        int e = tid + j*256, k = e>>6, s = e&63;
        dst[(size_t)(b*HD + k0 + k)*64 + s] = tilebuf[k][s];
    }
}

// ============ merged launch 3: tri (512 blocks) + transpose_vals (256) ======
__global__ __launch_bounds__(256,2) void l3_kernel(const __half* __restrict__ q,
        const __half* __restrict__ sk, const __half* __restrict__ tk,
        __half* __restrict__ w, float* __restrict__ rs, const __half* __restrict__ sv,
        const __half* __restrict__ tv, __half* __restrict__ svT, __half* __restrict__ tvT){
    extern __shared__ __align__(16) float dsm[];
    int bx = blockIdx.x;
    if (bx < 512){
        tri_body(q, sk, tk, w, rs, bx & 31, bx >> 5, dsm);
    } else {
        int local = bx - 512;
        tvals_body(sv, tv, svT, tvT, local & 7, (local >> 3) & 15, local >> 7, dsm);
    }
}

// ============ merged launch 4: ctx (256 blocks) + out sp0,1 (128) ===========
__global__ __launch_bounds__(256,2) void l5_kernel(const __half* __restrict__ E,
        const __half* __restrict__ svT, const __half* __restrict__ tvT,
        __half* __restrict__ cpart, const __half* __restrict__ query,
        const __half* __restrict__ WoT, float* __restrict__ opart){
    extern __shared__ __align__(16) float dsm[];
    int bx = blockIdx.x;
    if (bx < 256){
        int nt = bx & 3, sp = (bx >> 2) & 3, b = bx >> 4;
        ctx_body(E, svT, tvT, cpart, nt, sp, b, dsm);
    } else {
        int local = bx - 256;
        out_part_body(query, WoT, opart, local & 3, (local >> 2) & 15, local >> 6, dsm);
    }
}

// ============ projections: C = A[Mx1024] @ W + bias (half out) ==============
struct ProjArgs {
    const __half* A[5];
    const __half* WT[5];
    const float*  bias[5];
    __half*       C[5];
};

__global__ __launch_bounds__(256,2) void proj_mma(ProjArgs args){
    extern __shared__ __align__(16) float dsm[];
    int y = blockIdx.y;
    int task, mt;
    if (y < 16){ task=0; mt=y; } else { task = 1 + ((y-16)>>3); mt = (y-16)&7; }
    int bm = mt*128, bn = blockIdx.x*128;
    const __half* Ab   = args.A[task]  + (size_t)bm*QD;
    const __half* Bw   = args.WT[task] + (size_t)bn*QD;
    const float*  bias = args.bias[task];
    __half*       C    = args.C[task]  + (size_t)bm*OD + bn;
    MMA_PROLOG();
    const __half* Ap[4]; const __half* Bp[4];
    #pragma unroll
    for (int j=0;j<4;j++){
        Ap[j] = Ab + (size_t)row_[j]*QD + seg_[j]*8;
        Bp[j] = Bw + (size_t)row_[j]*QD + seg_[j]*8;
    }
    COPY_LOOP(16, Ap[j], Bp[j]);

    const float* bp = bias + bn + wn*64 + tig*2;
    #pragma unroll
    for (int mf=0;mf<2;mf++){
        int row = wm*32 + mf*16 + gid;
        __half* c0 = C + (size_t)row*OD + wn*64 + tig*2;
        #pragma unroll
        for (int nf=0;nf<8;nf++){
            float b0 = bp[nf*8], b1 = bp[nf*8+1];
            *(__half2*)(c0 + nf*8)        = __floats2half2_rn(acc[mf][nf][0]+b0, acc[mf][nf][1]+b1);
            *(__half2*)(c0 + nf*8 + 8*OD) = __floats2half2_rn(acc[mf][nf][2]+b0, acc[mf][nf][3]+b1);
        }
    }
}

// -------- prep: cvt inputs (4096) + transpose weights (1152) + zero rs ------
struct PrepArgs {
    const float* q; const float* s; const float* t;
    __half* qh; __half* sh; __half* th;
    const float* wsrc[6]; __half* wdst[6]; int K[6];
    float* rs;
};
__global__ void prep_kernel(PrepArgs a){
    __shared__ float tb[64][65];
    int bx = blockIdx.x, tid = threadIdx.x;
    if (bx < 4096){
        if (bx == 0){
            #pragma unroll
            for (int i=0;i<8;i++) a.rs[tid + i*256] = 0.f;
        }
        int gid = bx*256 + tid;
        const float4* src; uint2* dst; int off;
        if (gid < 524288){ src=(const float4*)a.q; dst=(uint2*)a.qh; off=gid; }
        else if (gid < 786432){ src=(const float4*)a.s; dst=(uint2*)a.sh; off=gid-524288; }
        else { src=(const float4*)a.t; dst=(uint2*)a.th; off=gid-786432; }
        float4 v = src[off];
        uint2 r; __half2* pr=(__half2*)&r;
        pr[0]=__floats2half2_rn(v.x,v.y); pr[1]=__floats2half2_rn(v.z,v.w);
        dst[off]=r;
    } else {
        int local = bx - 4096;
        int mid = local / 192;
        int rem = local % 192;
        int k0 = (rem >> 3) * 64;
        int n0 = (rem & 7) * 64;
        int K = a.K[mid];
        if (k0 >= K) return;
        const float* src = a.wsrc[mid];
        __half* dst = a.wdst[mid];
        #pragma unroll
        for (int j=0;j<16;j++){
            int e = tid + j*256, kk = e>>6, nn = e&63;
            tb[nn][kk] = src[(size_t)(k0+kk)*512 + n0+nn];
        }
        __syncthreads();
        #pragma unroll
        for (int j=0;j<16;j++){
            int e = tid + j*256, nn = e>>6, kk = e&63;
            dst[(size_t)(n0+nn)*K + k0+kk] = __float2half(tb[nn][kk]);
        }
    }
}

// reduce the 4 half split-K partials, apply 1/rowsum, emit half ctx
__global__ void ctx_reduce(const __half* __restrict__ part, const float* __restrict__ rs,
                           __half* __restrict__ ctx){
    int gid = blockIdx.x*256 + threadIdx.x;       // 4-elem id over 16*128*128
    int n4 = gid & 127; int rest = gid >> 7; int l = rest & 127; int b = rest >> 7;
    const uint2* p = (const uint2*)part;
    float a0=0,a1=0,a2=0,a3=0;
    #pragma unroll
    for (int sp=0; sp<4; sp++){
        uint2 u = p[ ((size_t)(b*4+sp)*128 + l)*128 + n4 ];
        __half2* pu = (__half2*)&u;
        float2 x = __half22float2(pu[0]), y = __half22float2(pu[1]);
        a0+=x.x; a1+=x.y; a2+=y.x; a3+=y.y;
    }
    float inv = 1.f / rs[b*128 + l];
    uint2 r; __half2* pr=(__half2*)&r;
    pr[0]=__floats2half2_rn(a0*inv, a1*inv); pr[1]=__floats2half2_rn(a2*inv, a3*inv);
    ((uint2*)ctx)[gid] = r;
}

// ----------------------------------------------------------------------------
extern "C" void kernel_launch(void* const* d_in, const int* in_sizes, int n_in,
                              void* d_out, int out_size) {
    const float* query = (const float*)d_in[0];
    const float* src   = (const float*)d_in[1];
    const float* trg   = (const float*)d_in[2];
    const float* Wq    = (const float*)d_in[3];
    const float* bq    = (const float*)d_in[4];
    const float* Ws    = (const float*)d_in[5];
    const float* bs    = (const float*)d_in[6];
    const float* Wt    = (const float*)d_in[7];
    const float* bt    = (const float*)d_in[8];
    const float* Wsv   = (const float*)d_in[9];
    const float* bsv   = (const float*)d_in[10];
    const float* Wtv   = (const float*)d_in[11];
    const float* btv   = (const float*)d_in[12];
    const float* Wo    = (const float*)d_in[13];
    const float* bo    = (const float*)d_in[14];
    float* out = (float*)d_out;

    __half *qryh,*srch,*trgh,*qh,*skh,*tkh,*svh,*tvh,*svTh,*tvTh,*wh,*ctxh,*wTh,*cparth;
    float *grs,*gpart;
    cudaGetSymbolAddress((void**)&qryh, g_qryh);
    cudaGetSymbolAddress((void**)&srch, g_srch);
    cudaGetSymbolAddress((void**)&trgh, g_trgh);
    cudaGetSymbolAddress((void**)&qh,   g_qh);
    cudaGetSymbolAddress((void**)&skh,  g_skh);
    cudaGetSymbolAddress((void**)&tkh,  g_tkh);
    cudaGetSymbolAddress((void**)&svh,  g_svh);
    cudaGetSymbolAddress((void**)&tvh,  g_tvh);
    cudaGetSymbolAddress((void**)&svTh, g_svTh);
    cudaGetSymbolAddress((void**)&tvTh, g_tvTh);
    cudaGetSymbolAddress((void**)&wh,   g_wh);
    cudaGetSymbolAddress((void**)&ctxh, g_ctxh);
    cudaGetSymbolAddress((void**)&wTh,  g_wTh);
    cudaGetSymbolAddress((void**)&cparth, g_parth);
    cudaGetSymbolAddress((void**)&grs,  g_rs);
    cudaGetSymbolAddress((void**)&gpart,g_part);

    static int smem_set = 0;
    if (!smem_set){
        cudaFuncSetAttribute(l3_kernel,       cudaFuncAttributeMaxDynamicSharedMemorySize, SMEM_MMA);
        cudaFuncSetAttribute(l5_kernel,       cudaFuncAttributeMaxDynamicSharedMemorySize, SMEM_MMA);
        cudaFuncSetAttribute(out_final_kernel,cudaFuncAttributeMaxDynamicSharedMemorySize, SMEM_MMA);
        cudaFuncSetAttribute(proj_mma,        cudaFuncAttributeMaxDynamicSharedMemorySize, SMEM_MMA);
        smem_set = 1;
    }

    __half* WqT  = wTh;
    __half* WsT  = wTh + 1*512*1024;
    __half* WtT  = wTh + 2*512*1024;
    __half* WsvT = wTh + 3*512*1024;
    __half* WtvT = wTh + 4*512*1024;
    __half* WoT  = wTh + 5*512*1024;

    PrepArgs pr;
    pr.q=query; pr.s=src; pr.t=trg; pr.qh=qryh; pr.sh=srch; pr.th=trgh;
    pr.wsrc[0]=Wq;  pr.wdst[0]=WqT;  pr.K[0]=1024;
    pr.wsrc[1]=Ws;  pr.wdst[1]=WsT;  pr.K[1]=1024;
    pr.wsrc[2]=Wt;  pr.wdst[2]=WtT;  pr.K[2]=1024;
    pr.wsrc[3]=Wsv; pr.wdst[3]=WsvT; pr.K[3]=1024;
    pr.wsrc[4]=Wtv; pr.wdst[4]=WtvT; pr.K[4]=1024;
    pr.wsrc[5]=Wo;  pr.wdst[5]=WoT;  pr.K[5]=1536;
    pr.rs = grs;

    ProjArgs pa;
    pa.A[0]=qryh;  pa.A[1]=srch; pa.A[2]=trgh; pa.A[3]=srch;  pa.A[4]=trgh;
    pa.WT[0]=WqT;  pa.WT[1]=WsT; pa.WT[2]=WtT; pa.WT[3]=WsvT; pa.WT[4]=WtvT;
    pa.bias[0]=bq; pa.bias[1]=bs; pa.bias[2]=bt; pa.bias[3]=bsv; pa.bias[4]=btv;
    pa.C[0]=qh;    pa.C[1]=skh;  pa.C[2]=tkh;  pa.C[3]=svh;   pa.C[4]=tvh;

    prep_kernel     <<<4096+1152,  256>>>(pr);
    proj_mma        <<<dim3(4,48), 256, SMEM_MMA>>>(pa);
    l3_kernel       <<<768,        256, SMEM_MMA>>>(qh, skh, tkh, wh, grs, svh, tvh, svTh, tvTh);
    l5_kernel       <<<384,        256, SMEM_MMA>>>(wh, svTh, tvTh, cparth, qryh, WoT, gpart);
    ctx_reduce      <<<1024,       256>>>(cparth, grs, ctxh);
    out_final_kernel<<<dim3(4,16), 256, SMEM_MMA>>>(ctxh, WoT, gpart, bo, out);
}